// round 1
// baseline (speedup 1.0000x reference)
#include <cuda_runtime.h>

// Problem constants (shapes fixed by the dataset).
#define C_IN   4096
#define BATCH  8192
#define C_OUT  4096
#define ROW_SPLIT 32

// Device-global scratch (no allocations allowed).
__device__ float g_noise[C_IN];
__device__ float g_a[C_IN];     // gamma * rsqrt(var+eps)
__device__ float g_d[C_IN];     // beta - mean * a
__device__ float g_psum[ROW_SPLIT * C_IN];
__device__ float g_psq [ROW_SPLIT * C_IN];

// ---------------------------------------------------------------------------
// Kernel 1: deterministic PoolRandom noise (LCG), single-threaded (the pool
// shuffle is inherently sequential). Pool lives in shared memory.
// ---------------------------------------------------------------------------
__global__ void noise_kernel() {
    __shared__ unsigned pool[C_IN];
    if (threadIdx.x == 0) {
        unsigned s = 123u;
        #pragma unroll 1
        for (int i = 0; i < C_IN; i++) {
            s = 65539u * s + 1u;       // mod 2^32 implicit
            pool[i] = s;
        }
        int nxt = C_IN - 1;
        #pragma unroll 1
        for (int i = 0; i < C_IN; i++) {
            nxt = (int)(pool[nxt] & (unsigned)(C_IN - 1));   // % 4096
            unsigned v = pool[nxt];
            g_noise[i] = (float)((double)v * 1e-9);
            s = 65539u * s + 1u;
            pool[nxt] = s;
        }
    }
}

// ---------------------------------------------------------------------------
// Kernel 2: per-channel partial sums of h and h^2, h = relu(x + noise).
// Grid (C_IN/256, ROW_SPLIT). Coalesced across channels; deterministic
// (fixed tree, no float atomics).
// ---------------------------------------------------------------------------
__global__ void stats_kernel(const float* __restrict__ x) {
    const int col = blockIdx.x * 256 + threadIdx.x;
    const int r0  = blockIdx.y * (BATCH / ROW_SPLIT);
    const float nz = g_noise[col];
    float s = 0.f, q = 0.f;
    const float* p = x + (size_t)r0 * C_IN + col;
    #pragma unroll 4
    for (int r = 0; r < BATCH / ROW_SPLIT; r++) {
        float h = p[(size_t)r * C_IN];
        h = fmaxf(h + nz, 0.f);
        s += h;
        q += h * h;
    }
    g_psum[blockIdx.y * C_IN + col] = s;
    g_psq [blockIdx.y * C_IN + col] = q;
}

// ---------------------------------------------------------------------------
// Kernel 3: reduce partials -> mean/var -> fold BN into per-channel a, d.
// ---------------------------------------------------------------------------
__global__ void finalize_kernel(const float* __restrict__ gamma,
                                const float* __restrict__ beta) {
    const int c = blockIdx.x * 256 + threadIdx.x;
    float s = 0.f, q = 0.f;
    #pragma unroll
    for (int i = 0; i < ROW_SPLIT; i++) {
        s += g_psum[i * C_IN + c];
        q += g_psq [i * C_IN + c];
    }
    const float mean = s * (1.f / BATCH);
    const float var  = q * (1.f / BATCH) - mean * mean;   // biased var
    const float rstd = rsqrtf(var + 0.8f);                 // BN eps = 0.8
    const float a = rstd * gamma[c];
    g_a[c] = a;
    g_d[c] = beta[c] - mean * a;
}

// ---------------------------------------------------------------------------
// Kernel 4: z = hn @ W^T + b, where hn is generated on the fly from x:
//   hn = relu(x + noise) * a + d
// Classic 128x128 SIMT fp32 tile, 256 threads, 8x8 per thread, BK=16.
// Both x and W are K-major (row-major, K contiguous) -> NT GEMM.
// ---------------------------------------------------------------------------
#define BM 128
#define BN 128
#define BK 16

__global__ __launch_bounds__(256, 2)
void gemm_kernel(const float* __restrict__ x,
                 const float* __restrict__ W,
                 const float* __restrict__ bias,
                 float* __restrict__ out) {
    __shared__ float As[BK][BM];
    __shared__ float Bs[BK][BN];

    const int tid = threadIdx.x;
    const int tx = tid & 15;       // 0..15 -> output cols
    const int ty = tid >> 4;       // 0..15 -> output rows
    const int rowBase = blockIdx.y * BM;
    const int colBase = blockIdx.x * BN;

    // Loader mapping: 256 threads load 128 rows x 16 cols per operand,
    // float4 per thread, 2 row-iterations.
    const int lr = tid >> 2;             // 0..63
    const int lc = (tid & 3) * 4;        // 0,4,8,12

    float acc[8][8] = {};

    for (int k0 = 0; k0 < C_IN; k0 += BK) {
        #pragma unroll
        for (int rr = 0; rr < BM; rr += 64) {
            const int row = lr + rr;
            // A operand: fused relu(x+noise)*a + d
            float4 v  = *(const float4*)(x + (size_t)(rowBase + row) * C_IN + k0 + lc);
            float4 nz = *(const float4*)(g_noise + k0 + lc);
            float4 av = *(const float4*)(g_a + k0 + lc);
            float4 dv = *(const float4*)(g_d + k0 + lc);
            As[lc + 0][row] = fmaxf(v.x + nz.x, 0.f) * av.x + dv.x;
            As[lc + 1][row] = fmaxf(v.y + nz.y, 0.f) * av.y + dv.y;
            As[lc + 2][row] = fmaxf(v.z + nz.z, 0.f) * av.z + dv.z;
            As[lc + 3][row] = fmaxf(v.w + nz.w, 0.f) * av.w + dv.w;
            // B operand: W row (colBase+row), K-slice
            float4 w = *(const float4*)(W + (size_t)(colBase + row) * C_IN + k0 + lc);
            Bs[lc + 0][row] = w.x;
            Bs[lc + 1][row] = w.y;
            Bs[lc + 2][row] = w.z;
            Bs[lc + 3][row] = w.w;
        }
        __syncthreads();

        #pragma unroll
        for (int k = 0; k < BK; k++) {
            float af[8], bf[8];
            *(float4*)&af[0] = *(const float4*)&As[k][ty * 8];
            *(float4*)&af[4] = *(const float4*)&As[k][ty * 8 + 4];
            *(float4*)&bf[0] = *(const float4*)&Bs[k][tx * 8];
            *(float4*)&bf[4] = *(const float4*)&Bs[k][tx * 8 + 4];
            #pragma unroll
            for (int i = 0; i < 8; i++)
                #pragma unroll
                for (int j = 0; j < 8; j++)
                    acc[i][j] = fmaf(af[i], bf[j], acc[i][j]);
        }
        __syncthreads();
    }

    // Epilogue: + bias, vectorized stores.
    #pragma unroll
    for (int i = 0; i < 8; i++) {
        const int row = rowBase + ty * 8 + i;
        #pragma unroll
        for (int j = 0; j < 8; j += 4) {
            const int col = colBase + tx * 8 + j;
            float4 bv = *(const float4*)(bias + col);
            float4 o;
            o.x = acc[i][j + 0] + bv.x;
            o.y = acc[i][j + 1] + bv.y;
            o.z = acc[i][j + 2] + bv.z;
            o.w = acc[i][j + 3] + bv.w;
            *(float4*)(out + (size_t)row * C_OUT + col) = o;
        }
    }
}

// ---------------------------------------------------------------------------
// Launch
// ---------------------------------------------------------------------------
extern "C" void kernel_launch(void* const* d_in, const int* in_sizes, int n_in,
                              void* d_out, int out_size) {
    const float* x     = (const float*)d_in[0];
    const float* gamma = (const float*)d_in[1];
    const float* beta  = (const float*)d_in[2];
    const float* W     = (const float*)d_in[3];
    const float* b     = (const float*)d_in[4];
    float* out = (float*)d_out;

    noise_kernel<<<1, 32>>>();
    stats_kernel<<<dim3(C_IN / 256, ROW_SPLIT), 256>>>(x);
    finalize_kernel<<<C_IN / 256, 256>>>(gamma, beta);
    gemm_kernel<<<dim3(C_OUT / BN, BATCH / BM), 256>>>(x, W, b, out);
}

// round 8
// speedup vs baseline: 1.2605x; 1.2605x over previous
#include <cuda_runtime.h>
#include <cuda_bf16.h>
#include <cstdint>

#define C_IN   4096
#define BATCH  8192
#define C_OUT  4096
#define ROW_SPLIT 32

// ---------------------------------------------------------------------------
// Device-global scratch — small (~1.1 MB).
// ---------------------------------------------------------------------------
__device__ float g_noise[C_IN];
__device__ float g_a[C_IN];
__device__ float g_d[C_IN];
__device__ float g_psum[ROW_SPLIT * C_IN];
__device__ float g_psq [ROW_SPLIT * C_IN];

// ---------------------------------------------------------------------------
// Helpers (family-portable: ldmatrix + mma.sync only; no cp.async, no mbarrier)
// ---------------------------------------------------------------------------
__device__ __forceinline__ uint32_t smem_u32(const void* p) {
    uint32_t a;
    asm("{ .reg .u64 t; cvta.to.shared.u64 t, %1; cvt.u32.u64 %0, t; }" : "=r"(a) : "l"(p));
    return a;
}
__device__ __forceinline__ void ldsm_x4(uint32_t addr, uint32_t& r0, uint32_t& r1,
                                        uint32_t& r2, uint32_t& r3) {
    asm volatile("ldmatrix.sync.aligned.m8n8.x4.shared.b16 {%0,%1,%2,%3}, [%4];"
                 : "=r"(r0), "=r"(r1), "=r"(r2), "=r"(r3) : "r"(addr));
}
__device__ __forceinline__ void mma16816(float& c0, float& c1, float& c2, float& c3,
                                         uint32_t a0, uint32_t a1, uint32_t a2, uint32_t a3,
                                         uint32_t b0, uint32_t b1) {
    asm volatile(
        "mma.sync.aligned.m16n8k16.row.col.f32.bf16.bf16.f32 "
        "{%0,%1,%2,%3}, {%4,%5,%6,%7}, {%8,%9}, {%0,%1,%2,%3};"
        : "+f"(c0), "+f"(c1), "+f"(c2), "+f"(c3)
        : "r"(a0), "r"(a1), "r"(a2), "r"(a3), "r"(b0), "r"(b1));
}

// ---------------------------------------------------------------------------
// Kernel 1: PoolRandom noise. LCG prefill via affine jump-ahead; only the
// 4096-step pool chase is serial.
// ---------------------------------------------------------------------------
__global__ void noise_kernel() {
    __shared__ unsigned seq[2 * C_IN];
    __shared__ unsigned outv[C_IN];
    const int tid = threadIdx.x;       // 256 threads, 32 states each

    {
        unsigned e = (unsigned)(tid * 32 + 1);
        unsigned ra = 1u, rc = 0u;
        unsigned ba = 65539u, bc = 1u;
        while (e) {
            if (e & 1u) { rc = ba * rc + bc; ra = ba * ra; }
            bc = ba * bc + bc;
            ba = ba * ba;
            e >>= 1u;
        }
        unsigned s = ra * 123u + rc;
        seq[tid * 32] = s;
        #pragma unroll
        for (int i = 1; i < 32; i++) { s = 65539u * s + 1u; seq[tid * 32 + i] = s; }
    }
    __syncthreads();

    if (tid == 0) {
        int nxt = C_IN - 1;
        #pragma unroll 1
        for (int i = 0; i < C_IN; i++) {
            nxt = (int)(seq[nxt] & (unsigned)(C_IN - 1));
            outv[i] = seq[nxt];
            seq[nxt] = seq[C_IN + i];
        }
    }
    __syncthreads();

    for (int i = tid; i < C_IN; i += 256)
        g_noise[i] = (float)((double)outv[i] * 1e-9);
}

// ---------------------------------------------------------------------------
// Kernel 2: per-channel partial sum / sumsq of h = relu(x + noise).
// ---------------------------------------------------------------------------
__global__ void stats_kernel(const float* __restrict__ x) {
    const int col = blockIdx.x * 256 + threadIdx.x;
    const int r0  = blockIdx.y * (BATCH / ROW_SPLIT);
    const float nz = g_noise[col];
    float s = 0.f, q = 0.f;
    const float* p = x + (size_t)r0 * C_IN + col;
    #pragma unroll 4
    for (int r = 0; r < BATCH / ROW_SPLIT; r++) {
        float h = fmaxf(p[(size_t)r * C_IN] + nz, 0.f);
        s += h; q += h * h;
    }
    g_psum[blockIdx.y * C_IN + col] = s;
    g_psq [blockIdx.y * C_IN + col] = q;
}

// ---------------------------------------------------------------------------
// Kernel 3: reduce partials -> BN fold:  hn = h*a + d
// ---------------------------------------------------------------------------
__global__ void finalize_kernel(const float* __restrict__ gamma,
                                const float* __restrict__ beta) {
    const int c = blockIdx.x * 256 + threadIdx.x;
    float s = 0.f, q = 0.f;
    #pragma unroll
    for (int i = 0; i < ROW_SPLIT; i++) { s += g_psum[i * C_IN + c]; q += g_psq[i * C_IN + c]; }
    const float mean = s * (1.f / BATCH);
    const float var  = q * (1.f / BATCH) - mean * mean;
    const float a = rsqrtf(var + 0.8f) * gamma[c];
    g_a[c] = a;
    g_d[c] = beta[c] - mean * a;
}

// ---------------------------------------------------------------------------
// Kernel 4: fused GEMM, conservative runtime envelope:
//   - static 40KB shared (no cudaFuncSetAttribute, no dynamic smem)
//   - plain float4 LDG register ping-pong prefetch (no cp.async)
//   - hn = relu(x+noise)*a + d and W split to bf16 hi/lo in-kernel
//   - 3-term mma.sync bf16: Ahi*Bhi + Ahi*Blo + Alo*Bhi, fp32 accum
// CTA tile 128x128, BK=32, 8 warps (warp tile 64x32 = 4x4 m16n8k16).
// ---------------------------------------------------------------------------
#define GBM 128
#define GBN 128
#define GBK 32
#define NCHUNK (C_IN / GBK)             // 128
#define PITCH 80                         // 64B data + 16B pad -> conflict-free ldmatrix
#define BF_TILE (128 * PITCH)            // 10240
#define AHI_OFF 0
#define ALO_OFF (1 * BF_TILE)
#define BHI_OFF (2 * BF_TILE)
#define BLO_OFF (3 * BF_TILE)
#define BF_BUF (4 * BF_TILE)             // 40960 bytes static shared

__device__ __forceinline__ void load_regs(float4 (&xr)[4], float4 (&wr)[4],
                                          const float* __restrict__ x,
                                          const float* __restrict__ W,
                                          int c, int tid, int rowBase, int colBase) {
    const int k0 = c * GBK;
    #pragma unroll
    for (int i = 0; i < 4; i++) {
        const int g = tid + i * 256;
        const int row = g >> 3, c16 = g & 7;
        xr[i] = *(const float4*)(x + (size_t)(rowBase + row) * C_IN + k0 + c16 * 4);
        wr[i] = *(const float4*)(W + (size_t)(colBase + row) * C_IN + k0 + c16 * 4);
    }
}

__device__ __forceinline__ void convert_phase(uint32_t sb, const float4 (&xr)[4],
                                              const float4 (&wr)[4], int c, int tid) {
    const int k0 = c * GBK;
    #pragma unroll
    for (int i = 0; i < 4; i++) {
        const int g = tid + i * 256;
        const int row = g >> 3, c16 = g & 7;
        const int k = k0 + c16 * 4;
        // A: hn = relu(x+noise)*a + d
        const float4 xv = xr[i];
        const float4 nz = *(const float4*)(g_noise + k);
        const float4 av = *(const float4*)(g_a + k);
        const float4 dv = *(const float4*)(g_d + k);
        float h0 = fmaxf(xv.x + nz.x, 0.f) * av.x + dv.x;
        float h1 = fmaxf(xv.y + nz.y, 0.f) * av.y + dv.y;
        float h2 = fmaxf(xv.z + nz.z, 0.f) * av.z + dv.z;
        float h3 = fmaxf(xv.w + nz.w, 0.f) * av.w + dv.w;
        __nv_bfloat16 e0 = __float2bfloat16(h0), e1 = __float2bfloat16(h1);
        __nv_bfloat16 e2 = __float2bfloat16(h2), e3 = __float2bfloat16(h3);
        __nv_bfloat162 hi01 = {e0, e1}, hi23 = {e2, e3};
        __nv_bfloat162 lo01 = {__float2bfloat16(h0 - __bfloat162float(e0)),
                               __float2bfloat16(h1 - __bfloat162float(e1))};
        __nv_bfloat162 lo23 = {__float2bfloat16(h2 - __bfloat162float(e2)),
                               __float2bfloat16(h3 - __bfloat162float(e3))};
        const uint32_t dsta = sb + row * PITCH + c16 * 8;
        asm volatile("st.shared.v2.b32 [%0], {%1,%2};" ::
            "r"(dsta + AHI_OFF), "r"(*(const uint32_t*)&hi01), "r"(*(const uint32_t*)&hi23) : "memory");
        asm volatile("st.shared.v2.b32 [%0], {%1,%2};" ::
            "r"(dsta + ALO_OFF), "r"(*(const uint32_t*)&lo01), "r"(*(const uint32_t*)&lo23) : "memory");
        // B: plain W split
        const float4 wv = wr[i];
        __nv_bfloat16 f0 = __float2bfloat16(wv.x), f1 = __float2bfloat16(wv.y);
        __nv_bfloat16 f2 = __float2bfloat16(wv.z), f3 = __float2bfloat16(wv.w);
        __nv_bfloat162 whi01 = {f0, f1}, whi23 = {f2, f3};
        __nv_bfloat162 wlo01 = {__float2bfloat16(wv.x - __bfloat162float(f0)),
                                __float2bfloat16(wv.y - __bfloat162float(f1))};
        __nv_bfloat162 wlo23 = {__float2bfloat16(wv.z - __bfloat162float(f2)),
                                __float2bfloat16(wv.w - __bfloat162float(f3))};
        asm volatile("st.shared.v2.b32 [%0], {%1,%2};" ::
            "r"(dsta + BHI_OFF), "r"(*(const uint32_t*)&whi01), "r"(*(const uint32_t*)&whi23) : "memory");
        asm volatile("st.shared.v2.b32 [%0], {%1,%2};" ::
            "r"(dsta + BLO_OFF), "r"(*(const uint32_t*)&wlo01), "r"(*(const uint32_t*)&wlo23) : "memory");
    }
}

__device__ __forceinline__ void mma_phase(uint32_t sb, float (&acc)[4][4][4],
                                          int warpARow, int warpBRow,
                                          int aRowSel, int aKByte,
                                          int bRowSel, int bKByte) {
    #pragma unroll
    for (int ks = 0; ks < 2; ks++) {
        const int kb = ks * 32;          // 16 bf16 per k-step
        uint32_t bhi[4][2], blo[4][2];
        #pragma unroll
        for (int bt = 0; bt < 2; bt++) {
            const uint32_t boff = (uint32_t)((warpBRow + bt * 16 + bRowSel) * PITCH
                                             + kb + bKByte);
            uint32_t r0, r1, r2, r3;
            ldsm_x4(sb + BHI_OFF + boff, r0, r1, r2, r3);
            bhi[bt * 2][0] = r0; bhi[bt * 2][1] = r1;
            bhi[bt * 2 + 1][0] = r2; bhi[bt * 2 + 1][1] = r3;
            ldsm_x4(sb + BLO_OFF + boff, r0, r1, r2, r3);
            blo[bt * 2][0] = r0; blo[bt * 2][1] = r1;
            blo[bt * 2 + 1][0] = r2; blo[bt * 2 + 1][1] = r3;
        }
        #pragma unroll
        for (int mt = 0; mt < 4; mt++) {
            const uint32_t aoff = (uint32_t)((warpARow + mt * 16 + aRowSel) * PITCH
                                             + kb + aKByte);
            uint32_t a0, a1, a2, a3, l0, l1, l2, l3;
            ldsm_x4(sb + AHI_OFF + aoff, a0, a1, a2, a3);
            ldsm_x4(sb + ALO_OFF + aoff, l0, l1, l2, l3);
            #pragma unroll
            for (int nt = 0; nt < 4; nt++) {
                mma16816(acc[mt][nt][0], acc[mt][nt][1], acc[mt][nt][2], acc[mt][nt][3],
                         a0, a1, a2, a3, bhi[nt][0], bhi[nt][1]);
                mma16816(acc[mt][nt][0], acc[mt][nt][1], acc[mt][nt][2], acc[mt][nt][3],
                         a0, a1, a2, a3, blo[nt][0], blo[nt][1]);
                mma16816(acc[mt][nt][0], acc[mt][nt][1], acc[mt][nt][2], acc[mt][nt][3],
                         l0, l1, l2, l3, bhi[nt][0], bhi[nt][1]);
            }
        }
    }
}

__global__ void __launch_bounds__(256)
gemm_mma_kernel(const float* __restrict__ x, const float* __restrict__ W,
                const float* __restrict__ bias, float* __restrict__ out) {
    __shared__ __align__(128) unsigned char smem[BF_BUF];
    const uint32_t sb = smem_u32(smem);
    const int tid = threadIdx.x;
    const int wid = tid >> 5, lane = tid & 31;
    const int rowBase = blockIdx.y * GBM;
    const int colBase = blockIdx.x * GBN;

    const int warpARow = (wid & 1) * 64;   // 2 warp-rows of 64
    const int warpBRow = (wid >> 1) * 32;  // 4 warp-cols of 32

    const int aRowSel = lane & 15;
    const int aKByte  = (lane >> 4) << 4;
    const int bRowSel = (lane & 7) + ((lane >> 4) << 3);
    const int bKByte  = ((lane >> 3) & 1) << 4;

    float acc[4][4][4];
    #pragma unroll
    for (int i = 0; i < 4; i++)
        #pragma unroll
        for (int j = 0; j < 4; j++)
            #pragma unroll
            for (int e = 0; e < 4; e++) acc[i][j][e] = 0.f;

    float4 xr0[4], wr0[4], xr1[4], wr1[4];
    load_regs(xr0, wr0, x, W, 0, tid, rowBase, colBase);

    #pragma unroll 1
    for (int c = 0; c < NCHUNK; c += 2) {
        // prefetch chunk c+1 while converting/MMAing chunk c
        load_regs(xr1, wr1, x, W, c + 1, tid, rowBase, colBase);
        convert_phase(sb, xr0, wr0, c, tid);
        __syncthreads();
        mma_phase(sb, acc, warpARow, warpBRow, aRowSel, aKByte, bRowSel, bKByte);
        __syncthreads();

        // prefetch chunk c+2 while converting/MMAing chunk c+1
        if (c + 2 < NCHUNK)
            load_regs(xr0, wr0, x, W, c + 2, tid, rowBase, colBase);
        convert_phase(sb, xr1, wr1, c + 1, tid);
        __syncthreads();
        mma_phase(sb, acc, warpARow, warpBRow, aRowSel, aKByte, bRowSel, bKByte);
        __syncthreads();
    }

    // Epilogue: direct stores with bias.
    const int lr = lane >> 2;
    const int lc = (lane & 3) * 2;
    #pragma unroll
    for (int nt = 0; nt < 4; nt++) {
        const int col = colBase + warpBRow + nt * 8 + lc;
        const float bv0 = bias[col];
        const float bv1 = bias[col + 1];
        #pragma unroll
        for (int mt = 0; mt < 4; mt++) {
            const int row0 = rowBase + warpARow + mt * 16 + lr;
            float2 v0 = { acc[mt][nt][0] + bv0, acc[mt][nt][1] + bv1 };
            float2 v1 = { acc[mt][nt][2] + bv0, acc[mt][nt][3] + bv1 };
            *(float2*)(out + (size_t)row0 * C_OUT + col)       = v0;
            *(float2*)(out + (size_t)(row0 + 8) * C_OUT + col) = v1;
        }
    }
}

// ---------------------------------------------------------------------------
// Launch — kernel launches only; no attribute calls, no dynamic smem.
// ---------------------------------------------------------------------------
extern "C" void kernel_launch(void* const* d_in, const int* in_sizes, int n_in,
                              void* d_out, int out_size) {
    const float* x     = (const float*)d_in[0];
    const float* gamma = (const float*)d_in[1];
    const float* beta  = (const float*)d_in[2];
    const float* W     = (const float*)d_in[3];
    const float* b     = (const float*)d_in[4];
    float* out = (float*)d_out;

    noise_kernel<<<1, 256>>>();
    stats_kernel<<<dim3(C_IN / 256, ROW_SPLIT), 256>>>(x);
    finalize_kernel<<<C_IN / 256, 256>>>(gamma, beta);
    gemm_mma_kernel<<<dim3(C_OUT / GBN, BATCH / GBM), 256>>>(x, W, b, out);
}

// round 11
// speedup vs baseline: 1.6423x; 1.3029x over previous
#include <cuda_runtime.h>
#include <cuda_bf16.h>
#include <cstdint>

#define C_IN   4096
#define BATCH  8192
#define C_OUT  4096
#define ROW_SPLIT 32

// ---------------------------------------------------------------------------
// Device-global scratch — small (~1.1 MB).
// ---------------------------------------------------------------------------
__device__ float g_noise[C_IN];
__device__ float g_a[C_IN];
__device__ float g_d[C_IN];
__device__ float g_psum[ROW_SPLIT * C_IN];
__device__ float g_psq [ROW_SPLIT * C_IN];

// ---------------------------------------------------------------------------
// Helpers
// ---------------------------------------------------------------------------
__device__ __forceinline__ uint32_t smem_u32(const void* p) {
    uint32_t a;
    asm("{ .reg .u64 t; cvta.to.shared.u64 t, %1; cvt.u32.u64 %0, t; }" : "=r"(a) : "l"(p));
    return a;
}
__device__ __forceinline__ void ldsm_x4(uint32_t addr, uint32_t& r0, uint32_t& r1,
                                        uint32_t& r2, uint32_t& r3) {
    asm volatile("ldmatrix.sync.aligned.m8n8.x4.shared.b16 {%0,%1,%2,%3}, [%4];"
                 : "=r"(r0), "=r"(r1), "=r"(r2), "=r"(r3) : "r"(addr));
}
__device__ __forceinline__ void mma16816(float& c0, float& c1, float& c2, float& c3,
                                         uint32_t a0, uint32_t a1, uint32_t a2, uint32_t a3,
                                         uint32_t b0, uint32_t b1) {
    asm volatile(
        "mma.sync.aligned.m16n8k16.row.col.f32.bf16.bf16.f32 "
        "{%0,%1,%2,%3}, {%4,%5,%6,%7}, {%8,%9}, {%0,%1,%2,%3};"
        : "+f"(c0), "+f"(c1), "+f"(c2), "+f"(c3)
        : "r"(a0), "r"(a1), "r"(a2), "r"(a3), "r"(b0), "r"(b1));
}
__device__ __forceinline__ uint32_t pack_bf16(float lo, float hi) {
    __nv_bfloat162 v = {__float2bfloat16(lo), __float2bfloat16(hi)};
    return *(const uint32_t*)&v;
}

// ---------------------------------------------------------------------------
// Kernel 1: PoolRandom noise (LCG jump-ahead prefill + serial pool chase).
// ---------------------------------------------------------------------------
__global__ void noise_kernel() {
    __shared__ unsigned seq[2 * C_IN];
    __shared__ unsigned outv[C_IN];
    const int tid = threadIdx.x;

    {
        unsigned e = (unsigned)(tid * 32 + 1);
        unsigned ra = 1u, rc = 0u;
        unsigned ba = 65539u, bc = 1u;
        while (e) {
            if (e & 1u) { rc = ba * rc + bc; ra = ba * ra; }
            bc = ba * bc + bc;
            ba = ba * ba;
            e >>= 1u;
        }
        unsigned s = ra * 123u + rc;
        seq[tid * 32] = s;
        #pragma unroll
        for (int i = 1; i < 32; i++) { s = 65539u * s + 1u; seq[tid * 32 + i] = s; }
    }
    __syncthreads();

    if (tid == 0) {
        int nxt = C_IN - 1;
        #pragma unroll 1
        for (int i = 0; i < C_IN; i++) {
            nxt = (int)(seq[nxt] & (unsigned)(C_IN - 1));
            outv[i] = seq[nxt];
            seq[nxt] = seq[C_IN + i];
        }
    }
    __syncthreads();

    for (int i = tid; i < C_IN; i += 256)
        g_noise[i] = (float)((double)outv[i] * 1e-9);
}

// ---------------------------------------------------------------------------
// Kernel 2: per-channel partial sum / sumsq of h = relu(x + noise).
// ---------------------------------------------------------------------------
__global__ void stats_kernel(const float* __restrict__ x) {
    const int col = blockIdx.x * 256 + threadIdx.x;
    const int r0  = blockIdx.y * (BATCH / ROW_SPLIT);
    const float nz = g_noise[col];
    float s = 0.f, q = 0.f;
    const float* p = x + (size_t)r0 * C_IN + col;
    #pragma unroll 4
    for (int r = 0; r < BATCH / ROW_SPLIT; r++) {
        float h = fmaxf(p[(size_t)r * C_IN] + nz, 0.f);
        s += h; q += h * h;
    }
    g_psum[blockIdx.y * C_IN + col] = s;
    g_psq [blockIdx.y * C_IN + col] = q;
}

// ---------------------------------------------------------------------------
// Kernel 3: reduce partials -> BN fold:  hn = h*a + d
// ---------------------------------------------------------------------------
__global__ void finalize_kernel(const float* __restrict__ gamma,
                                const float* __restrict__ beta) {
    const int c = blockIdx.x * 256 + threadIdx.x;
    float s = 0.f, q = 0.f;
    #pragma unroll
    for (int i = 0; i < ROW_SPLIT; i++) { s += g_psum[i * C_IN + c]; q += g_psq[i * C_IN + c]; }
    const float mean = s * (1.f / BATCH);
    const float var  = q * (1.f / BATCH) - mean * mean;
    const float a = rsqrtf(var + 0.8f) * gamma[c];
    g_a[c] = a;
    g_d[c] = beta[c] - mean * a;
}

// ---------------------------------------------------------------------------
// Kernel 4: fused GEMM, double-buffered smem, 1 barrier/chunk.
//   BK=16, pitch 48B (32B data + 16B pad -> conflict-free ldmatrix)
//   buffers: 2 x 4 tiles x 6144B = 49152B = 48KB static (no attribute call)
//   per chunk: mma(buf[c%2]) overlaps convert(c+1 -> buf[(c+1)%2])
//   Tile coverage: 256 threads x (1 row, 1 k-half of 8 elems) = 128x16 full.
// ---------------------------------------------------------------------------
#define GBM 128
#define GBN 128
#define GBK 16
#define NCHUNK (C_IN / GBK)             // 256
#define PITCH 48
#define BF_TILE (128 * PITCH)            // 6144
#define AHI_OFF 0
#define ALO_OFF (1 * BF_TILE)
#define BHI_OFF (2 * BF_TILE)
#define BLO_OFF (3 * BF_TILE)
#define BF_BUF (4 * BF_TILE)             // 24576
#define SMEM_TOT (2 * BF_BUF)            // 49152 = 48KB

__device__ __forceinline__ void load_regs(float4 (&xr)[2], float4 (&wr)[2],
                                          const float* __restrict__ x,
                                          const float* __restrict__ W,
                                          int c, int tid, int rowBase, int colBase) {
    const int k0 = c * GBK;
    const int row = tid >> 1, half = tid & 1;      // 128 rows x 2 k-halves
    const float* xp = x + (size_t)(rowBase + row) * C_IN + k0 + half * 8;
    const float* wp = W + (size_t)(colBase + row) * C_IN + k0 + half * 8;
    xr[0] = *(const float4*)xp;  xr[1] = *(const float4*)(xp + 4);
    wr[0] = *(const float4*)wp;  wr[1] = *(const float4*)(wp + 4);
}

__device__ __forceinline__ void convert_phase(uint32_t bbase, const float4 (&xr)[2],
                                              const float4 (&wr)[2], int c, int tid) {
    const int row = tid >> 1, half = tid & 1;
    const int k = c * GBK + half * 8;
    const uint32_t dst = bbase + row * PITCH + half * 16;

    // A: hn = relu(x+noise)*a + d -> 8 bf16 hi + 8 bf16 lo
    float h[8];
    #pragma unroll
    for (int j = 0; j < 2; j++) {
        const float4 xv = xr[j];
        const float4 nz = *(const float4*)(g_noise + k + j * 4);
        const float4 av = *(const float4*)(g_a + k + j * 4);
        const float4 dv = *(const float4*)(g_d + k + j * 4);
        h[j * 4 + 0] = fmaxf(xv.x + nz.x, 0.f) * av.x + dv.x;
        h[j * 4 + 1] = fmaxf(xv.y + nz.y, 0.f) * av.y + dv.y;
        h[j * 4 + 2] = fmaxf(xv.z + nz.z, 0.f) * av.z + dv.z;
        h[j * 4 + 3] = fmaxf(xv.w + nz.w, 0.f) * av.w + dv.w;
    }
    uint32_t hi[4], lo[4];
    #pragma unroll
    for (int j = 0; j < 4; j++) {
        float v0 = h[j * 2], v1 = h[j * 2 + 1];
        __nv_bfloat16 e0 = __float2bfloat16(v0), e1 = __float2bfloat16(v1);
        __nv_bfloat162 hp = {e0, e1};
        hi[j] = *(const uint32_t*)&hp;
        lo[j] = pack_bf16(v0 - __bfloat162float(e0), v1 - __bfloat162float(e1));
    }
    asm volatile("st.shared.v4.b32 [%0], {%1,%2,%3,%4};" ::
        "r"(dst + AHI_OFF), "r"(hi[0]), "r"(hi[1]), "r"(hi[2]), "r"(hi[3]) : "memory");
    asm volatile("st.shared.v4.b32 [%0], {%1,%2,%3,%4};" ::
        "r"(dst + ALO_OFF), "r"(lo[0]), "r"(lo[1]), "r"(lo[2]), "r"(lo[3]) : "memory");

    // B: W split -> 8 bf16 hi + 8 bf16 lo
    float w[8];
    #pragma unroll
    for (int j = 0; j < 2; j++) {
        const float4 wv = wr[j];
        w[j * 4 + 0] = wv.x; w[j * 4 + 1] = wv.y;
        w[j * 4 + 2] = wv.z; w[j * 4 + 3] = wv.w;
    }
    uint32_t whi[4], wlo[4];
    #pragma unroll
    for (int j = 0; j < 4; j++) {
        float v0 = w[j * 2], v1 = w[j * 2 + 1];
        __nv_bfloat16 e0 = __float2bfloat16(v0), e1 = __float2bfloat16(v1);
        __nv_bfloat162 hp = {e0, e1};
        whi[j] = *(const uint32_t*)&hp;
        wlo[j] = pack_bf16(v0 - __bfloat162float(e0), v1 - __bfloat162float(e1));
    }
    asm volatile("st.shared.v4.b32 [%0], {%1,%2,%3,%4};" ::
        "r"(dst + BHI_OFF), "r"(whi[0]), "r"(whi[1]), "r"(whi[2]), "r"(whi[3]) : "memory");
    asm volatile("st.shared.v4.b32 [%0], {%1,%2,%3,%4};" ::
        "r"(dst + BLO_OFF), "r"(wlo[0]), "r"(wlo[1]), "r"(wlo[2]), "r"(wlo[3]) : "memory");
}

__device__ __forceinline__ void mma_phase(uint32_t bbase, float (&acc)[4][4][4],
                                          int warpARow, int warpBRow,
                                          int aRowSel, int aKByte,
                                          int bRowSel, int bKByte) {
    uint32_t bhi[4][2], blo[4][2];
    #pragma unroll
    for (int bt = 0; bt < 2; bt++) {
        const uint32_t boff = (uint32_t)((warpBRow + bt * 16 + bRowSel) * PITCH + bKByte);
        uint32_t r0, r1, r2, r3;
        ldsm_x4(bbase + BHI_OFF + boff, r0, r1, r2, r3);
        bhi[bt * 2][0] = r0; bhi[bt * 2][1] = r1;
        bhi[bt * 2 + 1][0] = r2; bhi[bt * 2 + 1][1] = r3;
        ldsm_x4(bbase + BLO_OFF + boff, r0, r1, r2, r3);
        blo[bt * 2][0] = r0; blo[bt * 2][1] = r1;
        blo[bt * 2 + 1][0] = r2; blo[bt * 2 + 1][1] = r3;
    }
    #pragma unroll
    for (int mt = 0; mt < 4; mt++) {
        const uint32_t aoff = (uint32_t)((warpARow + mt * 16 + aRowSel) * PITCH + aKByte);
        uint32_t a0, a1, a2, a3, l0, l1, l2, l3;
        ldsm_x4(bbase + AHI_OFF + aoff, a0, a1, a2, a3);
        ldsm_x4(bbase + ALO_OFF + aoff, l0, l1, l2, l3);
        #pragma unroll
        for (int nt = 0; nt < 4; nt++) {
            mma16816(acc[mt][nt][0], acc[mt][nt][1], acc[mt][nt][2], acc[mt][nt][3],
                     a0, a1, a2, a3, bhi[nt][0], bhi[nt][1]);
            mma16816(acc[mt][nt][0], acc[mt][nt][1], acc[mt][nt][2], acc[mt][nt][3],
                     a0, a1, a2, a3, blo[nt][0], blo[nt][1]);
            mma16816(acc[mt][nt][0], acc[mt][nt][1], acc[mt][nt][2], acc[mt][nt][3],
                     l0, l1, l2, l3, bhi[nt][0], bhi[nt][1]);
        }
    }
}

__global__ void __launch_bounds__(256)
gemm_mma_kernel(const float* __restrict__ x, const float* __restrict__ W,
                const float* __restrict__ bias, float* __restrict__ out) {
    __shared__ __align__(128) unsigned char smem[SMEM_TOT];
    const uint32_t sb = smem_u32(smem);
    const uint32_t buf0 = sb, buf1 = sb + BF_BUF;
    const int tid = threadIdx.x;
    const int wid = tid >> 5, lane = tid & 31;
    const int rowBase = blockIdx.y * GBM;
    const int colBase = blockIdx.x * GBN;

    const int warpARow = (wid & 1) * 64;
    const int warpBRow = (wid >> 1) * 32;

    const int aRowSel = lane & 15;
    const int aKByte  = (lane >> 4) << 4;
    const int bRowSel = (lane & 7) + ((lane >> 4) << 3);
    const int bKByte  = ((lane >> 3) & 1) << 4;

    float acc[4][4][4];
    #pragma unroll
    for (int i = 0; i < 4; i++)
        #pragma unroll
        for (int j = 0; j < 4; j++)
            #pragma unroll
            for (int e = 0; e < 4; e++) acc[i][j][e] = 0.f;

    float4 xr0[2], wr0[2], xr1[2], wr1[2];
    load_regs(xr0, wr0, x, W, 0, tid, rowBase, colBase);
    convert_phase(buf0, xr0, wr0, 0, tid);
    load_regs(xr1, wr1, x, W, 1, tid, rowBase, colBase);
    __syncthreads();

    #pragma unroll 1
    for (int c = 0; c < NCHUNK; c += 2) {
        // iter c: mma(buf0) || convert(c+1 -> buf1); prefetch c+2
        if (c + 2 < NCHUNK) load_regs(xr0, wr0, x, W, c + 2, tid, rowBase, colBase);
        convert_phase(buf1, xr1, wr1, c + 1, tid);
        mma_phase(buf0, acc, warpARow, warpBRow, aRowSel, aKByte, bRowSel, bKByte);
        __syncthreads();
        // iter c+1: mma(buf1) || convert(c+2 -> buf0); prefetch c+3
        if (c + 3 < NCHUNK) load_regs(xr1, wr1, x, W, c + 3, tid, rowBase, colBase);
        if (c + 2 < NCHUNK) convert_phase(buf0, xr0, wr0, c + 2, tid);
        mma_phase(buf1, acc, warpARow, warpBRow, aRowSel, aKByte, bRowSel, bKByte);
        __syncthreads();
    }

    // Epilogue
    const int lr = lane >> 2;
    const int lc = (lane & 3) * 2;
    #pragma unroll
    for (int nt = 0; nt < 4; nt++) {
        const int col = colBase + warpBRow + nt * 8 + lc;
        const float bv0 = bias[col];
        const float bv1 = bias[col + 1];
        #pragma unroll
        for (int mt = 0; mt < 4; mt++) {
            const int row0 = rowBase + warpARow + mt * 16 + lr;
            float2 v0 = { acc[mt][nt][0] + bv0, acc[mt][nt][1] + bv1 };
            float2 v1 = { acc[mt][nt][2] + bv0, acc[mt][nt][3] + bv1 };
            *(float2*)(out + (size_t)row0 * C_OUT + col)       = v0;
            *(float2*)(out + (size_t)(row0 + 8) * C_OUT + col) = v1;
        }
    }
}

// ---------------------------------------------------------------------------
// Launch — kernel launches only.
// ---------------------------------------------------------------------------
extern "C" void kernel_launch(void* const* d_in, const int* in_sizes, int n_in,
                              void* d_out, int out_size) {
    const float* x     = (const float*)d_in[0];
    const float* gamma = (const float*)d_in[1];
    const float* beta  = (const float*)d_in[2];
    const float* W     = (const float*)d_in[3];
    const float* b     = (const float*)d_in[4];
    float* out = (float*)d_out;

    noise_kernel<<<1, 256>>>();
    stats_kernel<<<dim3(C_IN / 256, ROW_SPLIT), 256>>>(x);
    finalize_kernel<<<C_IN / 256, 256>>>(gamma, beta);
    gemm_mma_kernel<<<dim3(C_OUT / GBN, BATCH / GBM), 256>>>(x, W, b, out);
}

// round 12
// speedup vs baseline: 1.7181x; 1.0462x over previous
#include <cuda_runtime.h>
#include <cuda_bf16.h>
#include <cstdint>

#define C_IN   4096
#define BATCH  8192
#define C_OUT  4096
#define ROW_SPLIT 32

// ---------------------------------------------------------------------------
// Device-global scratch — small (~1.1 MB).
// ---------------------------------------------------------------------------
__device__ float g_noise[C_IN];
__device__ float g_a[C_IN];
__device__ float g_d[C_IN];
__device__ float g_psum[ROW_SPLIT * C_IN];
__device__ float g_psq [ROW_SPLIT * C_IN];

// ---------------------------------------------------------------------------
// Helpers
// ---------------------------------------------------------------------------
__device__ __forceinline__ uint32_t smem_u32(const void* p) {
    uint32_t a;
    asm("{ .reg .u64 t; cvta.to.shared.u64 t, %1; cvt.u32.u64 %0, t; }" : "=r"(a) : "l"(p));
    return a;
}
__device__ __forceinline__ void ldsm_x4(uint32_t addr, uint32_t& r0, uint32_t& r1,
                                        uint32_t& r2, uint32_t& r3) {
    asm volatile("ldmatrix.sync.aligned.m8n8.x4.shared.b16 {%0,%1,%2,%3}, [%4];"
                 : "=r"(r0), "=r"(r1), "=r"(r2), "=r"(r3) : "r"(addr));
}
__device__ __forceinline__ void mma16816(float& c0, float& c1, float& c2, float& c3,
                                         uint32_t a0, uint32_t a1, uint32_t a2, uint32_t a3,
                                         uint32_t b0, uint32_t b1) {
    asm volatile(
        "mma.sync.aligned.m16n8k16.row.col.f32.bf16.bf16.f32 "
        "{%0,%1,%2,%3}, {%4,%5,%6,%7}, {%8,%9}, {%0,%1,%2,%3};"
        : "+f"(c0), "+f"(c1), "+f"(c2), "+f"(c3)
        : "r"(a0), "r"(a1), "r"(a2), "r"(a3), "r"(b0), "r"(b1));
}
__device__ __forceinline__ uint32_t pack_bf16(float lo, float hi) {
    __nv_bfloat162 v = {__float2bfloat16(lo), __float2bfloat16(hi)};
    return *(const uint32_t*)&v;
}

// ---------------------------------------------------------------------------
// Kernel 1: PoolRandom noise (LCG jump-ahead prefill + serial pool chase).
// ---------------------------------------------------------------------------
__global__ void noise_kernel() {
    __shared__ unsigned seq[2 * C_IN];
    __shared__ unsigned outv[C_IN];
    const int tid = threadIdx.x;

    {
        unsigned e = (unsigned)(tid * 32 + 1);
        unsigned ra = 1u, rc = 0u;
        unsigned ba = 65539u, bc = 1u;
        while (e) {
            if (e & 1u) { rc = ba * rc + bc; ra = ba * ra; }
            bc = ba * bc + bc;
            ba = ba * ba;
            e >>= 1u;
        }
        unsigned s = ra * 123u + rc;
        seq[tid * 32] = s;
        #pragma unroll
        for (int i = 1; i < 32; i++) { s = 65539u * s + 1u; seq[tid * 32 + i] = s; }
    }
    __syncthreads();

    if (tid == 0) {
        int nxt = C_IN - 1;
        #pragma unroll 1
        for (int i = 0; i < C_IN; i++) {
            nxt = (int)(seq[nxt] & (unsigned)(C_IN - 1));
            outv[i] = seq[nxt];
            seq[nxt] = seq[C_IN + i];
        }
    }
    __syncthreads();

    for (int i = tid; i < C_IN; i += 256)
        g_noise[i] = (float)((double)outv[i] * 1e-9);
}

// ---------------------------------------------------------------------------
// Kernel 2: per-channel partial sum / sumsq of h = relu(x + noise).
// ---------------------------------------------------------------------------
__global__ void stats_kernel(const float* __restrict__ x) {
    const int col = blockIdx.x * 256 + threadIdx.x;
    const int r0  = blockIdx.y * (BATCH / ROW_SPLIT);
    const float nz = g_noise[col];
    float s = 0.f, q = 0.f;
    const float* p = x + (size_t)r0 * C_IN + col;
    #pragma unroll 4
    for (int r = 0; r < BATCH / ROW_SPLIT; r++) {
        float h = fmaxf(p[(size_t)r * C_IN] + nz, 0.f);
        s += h; q += h * h;
    }
    g_psum[blockIdx.y * C_IN + col] = s;
    g_psq [blockIdx.y * C_IN + col] = q;
}

// ---------------------------------------------------------------------------
// Kernel 3: reduce partials -> BN fold:  hn = h*a + d
// ---------------------------------------------------------------------------
__global__ void finalize_kernel(const float* __restrict__ gamma,
                                const float* __restrict__ beta) {
    const int c = blockIdx.x * 256 + threadIdx.x;
    float s = 0.f, q = 0.f;
    #pragma unroll
    for (int i = 0; i < ROW_SPLIT; i++) { s += g_psum[i * C_IN + c]; q += g_psq[i * C_IN + c]; }
    const float mean = s * (1.f / BATCH);
    const float var  = q * (1.f / BATCH) - mean * mean;
    const float a = rsqrtf(var + 0.8f) * gamma[c];
    g_a[c] = a;
    g_d[c] = beta[c] - mean * a;
}

// ---------------------------------------------------------------------------
// Kernel 4: fused GEMM, 512 threads / 16 warps, warp tile 32x32.
//   Double-buffered smem (48KB static), 1 barrier/chunk,
//   mma(buf[c%2]) overlaps convert(c+1 -> buf[(c+1)%2]).
//   3-term bf16 split, term-major MMA emission for ILP.
// ---------------------------------------------------------------------------
#define GBM 128
#define GBN 128
#define GBK 16
#define NTHREADS 512
#define NCHUNK (C_IN / GBK)             // 256
#define PITCH 48
#define BF_TILE (128 * PITCH)            // 6144
#define AHI_OFF 0
#define ALO_OFF (1 * BF_TILE)
#define BHI_OFF (2 * BF_TILE)
#define BLO_OFF (3 * BF_TILE)
#define BF_BUF (4 * BF_TILE)             // 24576
#define SMEM_TOT (2 * BF_BUF)            // 49152 = 48KB

// 512 threads: thread t owns (row = t>>2, quarter = t&3) -> one float4 per operand.
__device__ __forceinline__ void load_regs(float4& xr, float4& wr,
                                          const float* __restrict__ x,
                                          const float* __restrict__ W,
                                          int c, int tid, int rowBase, int colBase) {
    const int k0 = c * GBK;
    const int row = tid >> 2, q = tid & 3;
    xr = *(const float4*)(x + (size_t)(rowBase + row) * C_IN + k0 + q * 4);
    wr = *(const float4*)(W + (size_t)(colBase + row) * C_IN + k0 + q * 4);
}

__device__ __forceinline__ void convert_phase(uint32_t bbase, float4 xv, float4 wv,
                                              int c, int tid) {
    const int row = tid >> 2, q = tid & 3;
    const int k = c * GBK + q * 4;
    const uint32_t dst = bbase + row * PITCH + q * 8;

    // A: hn = relu(x+noise)*a + d -> 4 bf16 hi + 4 bf16 lo
    const float4 nz = *(const float4*)(g_noise + k);
    const float4 av = *(const float4*)(g_a + k);
    const float4 dv = *(const float4*)(g_d + k);
    float h0 = fmaxf(xv.x + nz.x, 0.f) * av.x + dv.x;
    float h1 = fmaxf(xv.y + nz.y, 0.f) * av.y + dv.y;
    float h2 = fmaxf(xv.z + nz.z, 0.f) * av.z + dv.z;
    float h3 = fmaxf(xv.w + nz.w, 0.f) * av.w + dv.w;
    __nv_bfloat16 e0 = __float2bfloat16(h0), e1 = __float2bfloat16(h1);
    __nv_bfloat16 e2 = __float2bfloat16(h2), e3 = __float2bfloat16(h3);
    __nv_bfloat162 hp01 = {e0, e1}, hp23 = {e2, e3};
    uint32_t hi0 = *(const uint32_t*)&hp01, hi1 = *(const uint32_t*)&hp23;
    uint32_t lo0 = pack_bf16(h0 - __bfloat162float(e0), h1 - __bfloat162float(e1));
    uint32_t lo1 = pack_bf16(h2 - __bfloat162float(e2), h3 - __bfloat162float(e3));
    asm volatile("st.shared.v2.b32 [%0], {%1,%2};" ::
        "r"(dst + AHI_OFF), "r"(hi0), "r"(hi1) : "memory");
    asm volatile("st.shared.v2.b32 [%0], {%1,%2};" ::
        "r"(dst + ALO_OFF), "r"(lo0), "r"(lo1) : "memory");

    // B: W split -> 4 bf16 hi + 4 bf16 lo
    __nv_bfloat16 f0 = __float2bfloat16(wv.x), f1 = __float2bfloat16(wv.y);
    __nv_bfloat16 f2 = __float2bfloat16(wv.z), f3 = __float2bfloat16(wv.w);
    __nv_bfloat162 wp01 = {f0, f1}, wp23 = {f2, f3};
    uint32_t whi0 = *(const uint32_t*)&wp01, whi1 = *(const uint32_t*)&wp23;
    uint32_t wlo0 = pack_bf16(wv.x - __bfloat162float(f0), wv.y - __bfloat162float(f1));
    uint32_t wlo1 = pack_bf16(wv.z - __bfloat162float(f2), wv.w - __bfloat162float(f3));
    asm volatile("st.shared.v2.b32 [%0], {%1,%2};" ::
        "r"(dst + BHI_OFF), "r"(whi0), "r"(whi1) : "memory");
    asm volatile("st.shared.v2.b32 [%0], {%1,%2};" ::
        "r"(dst + BLO_OFF), "r"(wlo0), "r"(wlo1) : "memory");
}

__device__ __forceinline__ void mma_phase(uint32_t bbase, float (&acc)[2][4][4],
                                          int warpARow, int warpBRow,
                                          int aRowSel, int aKByte,
                                          int bRowSel, int bKByte) {
    // Load all fragments first (8 ldsm), then emit term-major MMAs.
    uint32_t ahi[2][4], alo[2][4], bhi[4][2], blo[4][2];
    #pragma unroll
    for (int mt = 0; mt < 2; mt++) {
        const uint32_t aoff = (uint32_t)((warpARow + mt * 16 + aRowSel) * PITCH + aKByte);
        ldsm_x4(bbase + AHI_OFF + aoff, ahi[mt][0], ahi[mt][1], ahi[mt][2], ahi[mt][3]);
        ldsm_x4(bbase + ALO_OFF + aoff, alo[mt][0], alo[mt][1], alo[mt][2], alo[mt][3]);
    }
    #pragma unroll
    for (int bt = 0; bt < 2; bt++) {
        const uint32_t boff = (uint32_t)((warpBRow + bt * 16 + bRowSel) * PITCH + bKByte);
        uint32_t r0, r1, r2, r3;
        ldsm_x4(bbase + BHI_OFF + boff, r0, r1, r2, r3);
        bhi[bt * 2][0] = r0; bhi[bt * 2][1] = r1;
        bhi[bt * 2 + 1][0] = r2; bhi[bt * 2 + 1][1] = r3;
        ldsm_x4(bbase + BLO_OFF + boff, r0, r1, r2, r3);
        blo[bt * 2][0] = r0; blo[bt * 2][1] = r1;
        blo[bt * 2 + 1][0] = r2; blo[bt * 2 + 1][1] = r3;
    }
    // term 1: Ahi*Bhi  (8 independent MMAs)
    #pragma unroll
    for (int mt = 0; mt < 2; mt++)
        #pragma unroll
        for (int nt = 0; nt < 4; nt++)
            mma16816(acc[mt][nt][0], acc[mt][nt][1], acc[mt][nt][2], acc[mt][nt][3],
                     ahi[mt][0], ahi[mt][1], ahi[mt][2], ahi[mt][3],
                     bhi[nt][0], bhi[nt][1]);
    // term 2: Ahi*Blo
    #pragma unroll
    for (int mt = 0; mt < 2; mt++)
        #pragma unroll
        for (int nt = 0; nt < 4; nt++)
            mma16816(acc[mt][nt][0], acc[mt][nt][1], acc[mt][nt][2], acc[mt][nt][3],
                     ahi[mt][0], ahi[mt][1], ahi[mt][2], ahi[mt][3],
                     blo[nt][0], blo[nt][1]);
    // term 3: Alo*Bhi
    #pragma unroll
    for (int mt = 0; mt < 2; mt++)
        #pragma unroll
        for (int nt = 0; nt < 4; nt++)
            mma16816(acc[mt][nt][0], acc[mt][nt][1], acc[mt][nt][2], acc[mt][nt][3],
                     alo[mt][0], alo[mt][1], alo[mt][2], alo[mt][3],
                     bhi[nt][0], bhi[nt][1]);
}

__global__ void __launch_bounds__(NTHREADS)
gemm_mma_kernel(const float* __restrict__ x, const float* __restrict__ W,
                const float* __restrict__ bias, float* __restrict__ out) {
    __shared__ __align__(128) unsigned char smem[SMEM_TOT];
    const uint32_t sb = smem_u32(smem);
    const uint32_t buf0 = sb, buf1 = sb + BF_BUF;
    const int tid = threadIdx.x;
    const int wid = tid >> 5, lane = tid & 31;
    const int rowBase = blockIdx.y * GBM;
    const int colBase = blockIdx.x * GBN;

    // 16 warps: 4 warp-rows (M) x 4 warp-cols (N), warp tile 32x32
    const int warpARow = (wid & 3) * 32;
    const int warpBRow = (wid >> 2) * 32;

    const int aRowSel = lane & 15;
    const int aKByte  = (lane >> 4) << 4;
    const int bRowSel = (lane & 7) + ((lane >> 4) << 3);
    const int bKByte  = ((lane >> 3) & 1) << 4;

    float acc[2][4][4];
    #pragma unroll
    for (int i = 0; i < 2; i++)
        #pragma unroll
        for (int j = 0; j < 4; j++)
            #pragma unroll
            for (int e = 0; e < 4; e++) acc[i][j][e] = 0.f;

    float4 xr0, wr0, xr1, wr1;
    load_regs(xr0, wr0, x, W, 0, tid, rowBase, colBase);
    convert_phase(buf0, xr0, wr0, 0, tid);
    load_regs(xr1, wr1, x, W, 1, tid, rowBase, colBase);
    __syncthreads();

    #pragma unroll 1
    for (int c = 0; c < NCHUNK; c += 2) {
        // iter c: mma(buf0) || convert(c+1 -> buf1); prefetch c+2
        if (c + 2 < NCHUNK) load_regs(xr0, wr0, x, W, c + 2, tid, rowBase, colBase);
        convert_phase(buf1, xr1, wr1, c + 1, tid);
        mma_phase(buf0, acc, warpARow, warpBRow, aRowSel, aKByte, bRowSel, bKByte);
        __syncthreads();
        // iter c+1: mma(buf1) || convert(c+2 -> buf0); prefetch c+3
        if (c + 3 < NCHUNK) load_regs(xr1, wr1, x, W, c + 3, tid, rowBase, colBase);
        if (c + 2 < NCHUNK) convert_phase(buf0, xr0, wr0, c + 2, tid);
        mma_phase(buf1, acc, warpARow, warpBRow, aRowSel, aKByte, bRowSel, bKByte);
        __syncthreads();
    }

    // Epilogue
    const int lr = lane >> 2;
    const int lc = (lane & 3) * 2;
    #pragma unroll
    for (int nt = 0; nt < 4; nt++) {
        const int col = colBase + warpBRow + nt * 8 + lc;
        const float bv0 = bias[col];
        const float bv1 = bias[col + 1];
        #pragma unroll
        for (int mt = 0; mt < 2; mt++) {
            const int row0 = rowBase + warpARow + mt * 16 + lr;
            float2 v0 = { acc[mt][nt][0] + bv0, acc[mt][nt][1] + bv1 };
            float2 v1 = { acc[mt][nt][2] + bv0, acc[mt][nt][3] + bv1 };
            *(float2*)(out + (size_t)row0 * C_OUT + col)       = v0;
            *(float2*)(out + (size_t)(row0 + 8) * C_OUT + col) = v1;
        }
    }
}

// ---------------------------------------------------------------------------
// Launch — kernel launches only.
// ---------------------------------------------------------------------------
extern "C" void kernel_launch(void* const* d_in, const int* in_sizes, int n_in,
                              void* d_out, int out_size) {
    const float* x     = (const float*)d_in[0];
    const float* gamma = (const float*)d_in[1];
    const float* beta  = (const float*)d_in[2];
    const float* W     = (const float*)d_in[3];
    const float* b     = (const float*)d_in[4];
    float* out = (float*)d_out;

    noise_kernel<<<1, 256>>>();
    stats_kernel<<<dim3(C_IN / 256, ROW_SPLIT), 256>>>(x);
    finalize_kernel<<<C_IN / 256, 256>>>(gamma, beta);
    gemm_mma_kernel<<<dim3(C_OUT / GBN, BATCH / GBM), NTHREADS>>>(x, W, b, out);
}

// round 13
// speedup vs baseline: 1.7186x; 1.0003x over previous
#include <cuda_runtime.h>
#include <cuda_bf16.h>
#include <cstdint>

#define C_IN   4096
#define BATCH  8192
#define C_OUT  4096
#define ROW_SPLIT 32

// ---------------------------------------------------------------------------
// Device-global scratch — small (~1.1 MB).
// ---------------------------------------------------------------------------
__device__ float g_noise[C_IN];
__device__ float g_a[C_IN];
__device__ float g_d[C_IN];
__device__ float g_psum[ROW_SPLIT * C_IN];
__device__ float g_psq [ROW_SPLIT * C_IN];

// ---------------------------------------------------------------------------
// Helpers
// ---------------------------------------------------------------------------
__device__ __forceinline__ uint32_t smem_u32(const void* p) {
    uint32_t a;
    asm("{ .reg .u64 t; cvta.to.shared.u64 t, %1; cvt.u32.u64 %0, t; }" : "=r"(a) : "l"(p));
    return a;
}
__device__ __forceinline__ void ldsm_x4(uint32_t addr, uint32_t& r0, uint32_t& r1,
                                        uint32_t& r2, uint32_t& r3) {
    asm volatile("ldmatrix.sync.aligned.m8n8.x4.shared.b16 {%0,%1,%2,%3}, [%4];"
                 : "=r"(r0), "=r"(r1), "=r"(r2), "=r"(r3) : "r"(addr));
}
__device__ __forceinline__ void mma16816(float& c0, float& c1, float& c2, float& c3,
                                         uint32_t a0, uint32_t a1, uint32_t a2, uint32_t a3,
                                         uint32_t b0, uint32_t b1) {
    asm volatile(
        "mma.sync.aligned.m16n8k16.row.col.f32.bf16.bf16.f32 "
        "{%0,%1,%2,%3}, {%4,%5,%6,%7}, {%8,%9}, {%0,%1,%2,%3};"
        : "+f"(c0), "+f"(c1), "+f"(c2), "+f"(c3)
        : "r"(a0), "r"(a1), "r"(a2), "r"(a3), "r"(b0), "r"(b1));
}
__device__ __forceinline__ uint32_t pack_bf16(float lo, float hi) {
    __nv_bfloat162 v = {__float2bfloat16(lo), __float2bfloat16(hi)};
    return *(const uint32_t*)&v;
}

// ---------------------------------------------------------------------------
// Kernel 1: PoolRandom noise (LCG jump-ahead prefill + serial pool chase).
// ---------------------------------------------------------------------------
__global__ void noise_kernel() {
    __shared__ unsigned seq[2 * C_IN];
    __shared__ unsigned outv[C_IN];
    const int tid = threadIdx.x;

    {
        unsigned e = (unsigned)(tid * 32 + 1);
        unsigned ra = 1u, rc = 0u;
        unsigned ba = 65539u, bc = 1u;
        while (e) {
            if (e & 1u) { rc = ba * rc + bc; ra = ba * ra; }
            bc = ba * bc + bc;
            ba = ba * ba;
            e >>= 1u;
        }
        unsigned s = ra * 123u + rc;
        seq[tid * 32] = s;
        #pragma unroll
        for (int i = 1; i < 32; i++) { s = 65539u * s + 1u; seq[tid * 32 + i] = s; }
    }
    __syncthreads();

    if (tid == 0) {
        int nxt = C_IN - 1;
        #pragma unroll 1
        for (int i = 0; i < C_IN; i++) {
            nxt = (int)(seq[nxt] & (unsigned)(C_IN - 1));
            outv[i] = seq[nxt];
            seq[nxt] = seq[C_IN + i];
        }
    }
    __syncthreads();

    for (int i = tid; i < C_IN; i += 256)
        g_noise[i] = (float)((double)outv[i] * 1e-9);
}

// ---------------------------------------------------------------------------
// Kernel 2: per-channel partial sum / sumsq of h = relu(x + noise).
// ---------------------------------------------------------------------------
__global__ void stats_kernel(const float* __restrict__ x) {
    const int col = blockIdx.x * 256 + threadIdx.x;
    const int r0  = blockIdx.y * (BATCH / ROW_SPLIT);
    const float nz = g_noise[col];
    float s = 0.f, q = 0.f;
    const float* p = x + (size_t)r0 * C_IN + col;
    #pragma unroll 4
    for (int r = 0; r < BATCH / ROW_SPLIT; r++) {
        float h = fmaxf(p[(size_t)r * C_IN] + nz, 0.f);
        s += h; q += h * h;
    }
    g_psum[blockIdx.y * C_IN + col] = s;
    g_psq [blockIdx.y * C_IN + col] = q;
}

// ---------------------------------------------------------------------------
// Kernel 3: reduce partials -> BN fold:  hn = h*a + d
// ---------------------------------------------------------------------------
__global__ void finalize_kernel(const float* __restrict__ gamma,
                                const float* __restrict__ beta) {
    const int c = blockIdx.x * 256 + threadIdx.x;
    float s = 0.f, q = 0.f;
    #pragma unroll
    for (int i = 0; i < ROW_SPLIT; i++) { s += g_psum[i * C_IN + c]; q += g_psq[i * C_IN + c]; }
    const float mean = s * (1.f / BATCH);
    const float var  = q * (1.f / BATCH) - mean * mean;
    const float a = rsqrtf(var + 0.8f) * gamma[c];
    g_a[c] = a;
    g_d[c] = beta[c] - mean * a;
}

// ---------------------------------------------------------------------------
// Kernel 4: fused GEMM, 512 threads / 16 warps, warp tile 32x32.
//   Double-buffered smem (48KB static), 1 barrier/chunk,
//   mma(buf[c%2]) overlaps convert(c+1 -> buf[(c+1)%2]).
//   3-term bf16 split, term-major MMA emission for ILP.
// ---------------------------------------------------------------------------
#define GBM 128
#define GBN 128
#define GBK 16
#define NTHREADS 512
#define NCHUNK (C_IN / GBK)             // 256
#define PITCH 48
#define BF_TILE (128 * PITCH)            // 6144
#define AHI_OFF 0
#define ALO_OFF (1 * BF_TILE)
#define BHI_OFF (2 * BF_TILE)
#define BLO_OFF (3 * BF_TILE)
#define BF_BUF (4 * BF_TILE)             // 24576
#define SMEM_TOT (2 * BF_BUF)            // 49152 = 48KB

// 512 threads: thread t owns (row = t>>2, quarter = t&3) -> one float4 per operand.
__device__ __forceinline__ void load_regs(float4& xr, float4& wr,
                                          const float* __restrict__ x,
                                          const float* __restrict__ W,
                                          int c, int tid, int rowBase, int colBase) {
    const int k0 = c * GBK;
    const int row = tid >> 2, q = tid & 3;
    xr = *(const float4*)(x + (size_t)(rowBase + row) * C_IN + k0 + q * 4);
    wr = *(const float4*)(W + (size_t)(colBase + row) * C_IN + k0 + q * 4);
}

__device__ __forceinline__ void convert_phase(uint32_t bbase, float4 xv, float4 wv,
                                              int c, int tid) {
    const int row = tid >> 2, q = tid & 3;
    const int k = c * GBK + q * 4;
    const uint32_t dst = bbase + row * PITCH + q * 8;

    // A: hn = relu(x+noise)*a + d -> 4 bf16 hi + 4 bf16 lo
    const float4 nz = *(const float4*)(g_noise + k);
    const float4 av = *(const float4*)(g_a + k);
    const float4 dv = *(const float4*)(g_d + k);
    float h0 = fmaxf(xv.x + nz.x, 0.f) * av.x + dv.x;
    float h1 = fmaxf(xv.y + nz.y, 0.f) * av.y + dv.y;
    float h2 = fmaxf(xv.z + nz.z, 0.f) * av.z + dv.z;
    float h3 = fmaxf(xv.w + nz.w, 0.f) * av.w + dv.w;
    __nv_bfloat16 e0 = __float2bfloat16(h0), e1 = __float2bfloat16(h1);
    __nv_bfloat16 e2 = __float2bfloat16(h2), e3 = __float2bfloat16(h3);
    __nv_bfloat162 hp01 = {e0, e1}, hp23 = {e2, e3};
    uint32_t hi0 = *(const uint32_t*)&hp01, hi1 = *(const uint32_t*)&hp23;
    uint32_t lo0 = pack_bf16(h0 - __bfloat162float(e0), h1 - __bfloat162float(e1));
    uint32_t lo1 = pack_bf16(h2 - __bfloat162float(e2), h3 - __bfloat162float(e3));
    asm volatile("st.shared.v2.b32 [%0], {%1,%2};" ::
        "r"(dst + AHI_OFF), "r"(hi0), "r"(hi1) : "memory");
    asm volatile("st.shared.v2.b32 [%0], {%1,%2};" ::
        "r"(dst + ALO_OFF), "r"(lo0), "r"(lo1) : "memory");

    // B: W split -> 4 bf16 hi + 4 bf16 lo
    __nv_bfloat16 f0 = __float2bfloat16(wv.x), f1 = __float2bfloat16(wv.y);
    __nv_bfloat16 f2 = __float2bfloat16(wv.z), f3 = __float2bfloat16(wv.w);
    __nv_bfloat162 wp01 = {f0, f1}, wp23 = {f2, f3};
    uint32_t whi0 = *(const uint32_t*)&wp01, whi1 = *(const uint32_t*)&wp23;
    uint32_t wlo0 = pack_bf16(wv.x - __bfloat162float(f0), wv.y - __bfloat162float(f1));
    uint32_t wlo1 = pack_bf16(wv.z - __bfloat162float(f2), wv.w - __bfloat162float(f3));
    asm volatile("st.shared.v2.b32 [%0], {%1,%2};" ::
        "r"(dst + BHI_OFF), "r"(whi0), "r"(whi1) : "memory");
    asm volatile("st.shared.v2.b32 [%0], {%1,%2};" ::
        "r"(dst + BLO_OFF), "r"(wlo0), "r"(wlo1) : "memory");
}

__device__ __forceinline__ void mma_phase(uint32_t bbase, float (&acc)[2][4][4],
                                          int warpARow, int warpBRow,
                                          int aRowSel, int aKByte,
                                          int bRowSel, int bKByte) {
    // Load all fragments first (8 ldsm), then emit term-major MMAs.
    uint32_t ahi[2][4], alo[2][4], bhi[4][2], blo[4][2];
    #pragma unroll
    for (int mt = 0; mt < 2; mt++) {
        const uint32_t aoff = (uint32_t)((warpARow + mt * 16 + aRowSel) * PITCH + aKByte);
        ldsm_x4(bbase + AHI_OFF + aoff, ahi[mt][0], ahi[mt][1], ahi[mt][2], ahi[mt][3]);
        ldsm_x4(bbase + ALO_OFF + aoff, alo[mt][0], alo[mt][1], alo[mt][2], alo[mt][3]);
    }
    #pragma unroll
    for (int bt = 0; bt < 2; bt++) {
        const uint32_t boff = (uint32_t)((warpBRow + bt * 16 + bRowSel) * PITCH + bKByte);
        uint32_t r0, r1, r2, r3;
        ldsm_x4(bbase + BHI_OFF + boff, r0, r1, r2, r3);
        bhi[bt * 2][0] = r0; bhi[bt * 2][1] = r1;
        bhi[bt * 2 + 1][0] = r2; bhi[bt * 2 + 1][1] = r3;
        ldsm_x4(bbase + BLO_OFF + boff, r0, r1, r2, r3);
        blo[bt * 2][0] = r0; blo[bt * 2][1] = r1;
        blo[bt * 2 + 1][0] = r2; blo[bt * 2 + 1][1] = r3;
    }
    // term 1: Ahi*Bhi  (8 independent MMAs)
    #pragma unroll
    for (int mt = 0; mt < 2; mt++)
        #pragma unroll
        for (int nt = 0; nt < 4; nt++)
            mma16816(acc[mt][nt][0], acc[mt][nt][1], acc[mt][nt][2], acc[mt][nt][3],
                     ahi[mt][0], ahi[mt][1], ahi[mt][2], ahi[mt][3],
                     bhi[nt][0], bhi[nt][1]);
    // term 2: Ahi*Blo
    #pragma unroll
    for (int mt = 0; mt < 2; mt++)
        #pragma unroll
        for (int nt = 0; nt < 4; nt++)
            mma16816(acc[mt][nt][0], acc[mt][nt][1], acc[mt][nt][2], acc[mt][nt][3],
                     ahi[mt][0], ahi[mt][1], ahi[mt][2], ahi[mt][3],
                     blo[nt][0], blo[nt][1]);
    // term 3: Alo*Bhi
    #pragma unroll
    for (int mt = 0; mt < 2; mt++)
        #pragma unroll
        for (int nt = 0; nt < 4; nt++)
            mma16816(acc[mt][nt][0], acc[mt][nt][1], acc[mt][nt][2], acc[mt][nt][3],
                     alo[mt][0], alo[mt][1], alo[mt][2], alo[mt][3],
                     bhi[nt][0], bhi[nt][1]);
}

__global__ void __launch_bounds__(NTHREADS)
gemm_mma_kernel(const float* __restrict__ x, const float* __restrict__ W,
                const float* __restrict__ bias, float* __restrict__ out) {
    __shared__ __align__(128) unsigned char smem[SMEM_TOT];
    const uint32_t sb = smem_u32(smem);
    const uint32_t buf0 = sb, buf1 = sb + BF_BUF;
    const int tid = threadIdx.x;
    const int wid = tid >> 5, lane = tid & 31;
    const int rowBase = blockIdx.y * GBM;
    const int colBase = blockIdx.x * GBN;

    // 16 warps: 4 warp-rows (M) x 4 warp-cols (N), warp tile 32x32
    const int warpARow = (wid & 3) * 32;
    const int warpBRow = (wid >> 2) * 32;

    const int aRowSel = lane & 15;
    const int aKByte  = (lane >> 4) << 4;
    const int bRowSel = (lane & 7) + ((lane >> 4) << 3);
    const int bKByte  = ((lane >> 3) & 1) << 4;

    float acc[2][4][4];
    #pragma unroll
    for (int i = 0; i < 2; i++)
        #pragma unroll
        for (int j = 0; j < 4; j++)
            #pragma unroll
            for (int e = 0; e < 4; e++) acc[i][j][e] = 0.f;

    float4 xr0, wr0, xr1, wr1;
    load_regs(xr0, wr0, x, W, 0, tid, rowBase, colBase);
    convert_phase(buf0, xr0, wr0, 0, tid);
    load_regs(xr1, wr1, x, W, 1, tid, rowBase, colBase);
    __syncthreads();

    #pragma unroll 1
    for (int c = 0; c < NCHUNK; c += 2) {
        // iter c: mma(buf0) || convert(c+1 -> buf1); prefetch c+2
        if (c + 2 < NCHUNK) load_regs(xr0, wr0, x, W, c + 2, tid, rowBase, colBase);
        convert_phase(buf1, xr1, wr1, c + 1, tid);
        mma_phase(buf0, acc, warpARow, warpBRow, aRowSel, aKByte, bRowSel, bKByte);
        __syncthreads();
        // iter c+1: mma(buf1) || convert(c+2 -> buf0); prefetch c+3
        if (c + 3 < NCHUNK) load_regs(xr1, wr1, x, W, c + 3, tid, rowBase, colBase);
        if (c + 2 < NCHUNK) convert_phase(buf0, xr0, wr0, c + 2, tid);
        mma_phase(buf1, acc, warpARow, warpBRow, aRowSel, aKByte, bRowSel, bKByte);
        __syncthreads();
    }

    // Epilogue
    const int lr = lane >> 2;
    const int lc = (lane & 3) * 2;
    #pragma unroll
    for (int nt = 0; nt < 4; nt++) {
        const int col = colBase + warpBRow + nt * 8 + lc;
        const float bv0 = bias[col];
        const float bv1 = bias[col + 1];
        #pragma unroll
        for (int mt = 0; mt < 2; mt++) {
            const int row0 = rowBase + warpARow + mt * 16 + lr;
            float2 v0 = { acc[mt][nt][0] + bv0, acc[mt][nt][1] + bv1 };
            float2 v1 = { acc[mt][nt][2] + bv0, acc[mt][nt][3] + bv1 };
            *(float2*)(out + (size_t)row0 * C_OUT + col)       = v0;
            *(float2*)(out + (size_t)(row0 + 8) * C_OUT + col) = v1;
        }
    }
}

// ---------------------------------------------------------------------------
// Launch — kernel launches only.
// ---------------------------------------------------------------------------
extern "C" void kernel_launch(void* const* d_in, const int* in_sizes, int n_in,
                              void* d_out, int out_size) {
    const float* x     = (const float*)d_in[0];
    const float* gamma = (const float*)d_in[1];
    const float* beta  = (const float*)d_in[2];
    const float* W     = (const float*)d_in[3];
    const float* b     = (const float*)d_in[4];
    float* out = (float*)d_out;

    noise_kernel<<<1, 256>>>();
    stats_kernel<<<dim3(C_IN / 256, ROW_SPLIT), 256>>>(x);
    finalize_kernel<<<C_IN / 256, 256>>>(gamma, beta);
    gemm_mma_kernel<<<dim3(C_OUT / GBN, BATCH / GBM), NTHREADS>>>(x, W, b, out);
}